// round 10
// baseline (speedup 1.0000x reference)
#include <cuda_runtime.h>
#include <cuda_fp16.h>
#include <cstdint>

#define DI __device__ __forceinline__

// problem dims
#define CC   2048
#define WWD  96
#define HWP  4608          // 48*96
#define NCOL 384           // 4*96 GEMM columns
#define NSTEP 94

// GEMM tiling
#define BM 64
#define BN 96
#define BK 128
#define KITER (CC/BK)      // 16
#define NST 3
#define AST 136            // padded fp16 row stride (128+8) -> conflict-free ldmatrix
#define A_H (BM*AST)       // 8704 halfs
#define B_H (BN*AST)       // 13056 halfs
#define STG (A_H+B_H)      // 21760 halfs / stage
#define SMEM_BYTES (NST*STG*2)   // 130560 B
#define TPAD 72            // transpose tile stride (64 + 8 halfs)
#define NCTA 128           // 32 x 4 grid, all co-resident (1 CTA/SM)

#define AUNITS 1024        // A: 64 rows x 16 16B-units
#define TUNITS 2560        // A + B (96 x 16)

// device scratch (static; allocation-rule safe)
__device__ __half g_w[(size_t)CC * CC];            // 8.4 MB, L2-resident
__device__ __half g_carry[2][(size_t)NCOL * CC];   // 2 x 1.5 MB ping-pong
__device__ unsigned g_bar;                          // grid barrier counter (memset to 0 per launch)

// ---------------- PTX helpers (base sm_103 ISA only) ----------------
DI uint32_t smem_u32(const void* p) {
    uint32_t a;
    asm("{ .reg .u64 t; cvta.to.shared.u64 t, %1; cvt.u32.u64 %0, t; }" : "=r"(a) : "l"(p));
    return a;
}
DI void cp16(uint32_t s, const void* g) {
    asm volatile("cp.async.cg.shared.global [%0], [%1], 16;" :: "r"(s), "l"(g) : "memory");
}
DI void cp_commit() { asm volatile("cp.async.commit_group;" ::: "memory"); }
DI void cp_wait1()  { asm volatile("cp.async.wait_group 1;" ::: "memory"); }

DI void ldsm4(uint32_t a, uint32_t* r) {
    asm volatile("ldmatrix.sync.aligned.m8n8.x4.shared.b16 {%0,%1,%2,%3},[%4];"
        : "=r"(r[0]), "=r"(r[1]), "=r"(r[2]), "=r"(r[3]) : "r"(a));
}
DI void mma16816(float* d, const uint32_t* a, uint32_t b0, uint32_t b1) {
    asm volatile(
        "mma.sync.aligned.m16n8k16.row.col.f32.f16.f16.f32 "
        "{%0,%1,%2,%3},{%4,%5,%6,%7},{%8,%9},{%0,%1,%2,%3};"
        : "+f"(d[0]), "+f"(d[1]), "+f"(d[2]), "+f"(d[3])
        : "r"(a[0]), "r"(a[1]), "r"(a[2]), "r"(a[3]), "r"(b0), "r"(b1));
}

// ---------------- persistent all-steps kernel ----------------
__global__ void __launch_bounds__(256, 1)
steps_kernel(const float* __restrict__ bias,
             const float* __restrict__ fea, float* __restrict__ out)
{
    extern __shared__ __half sm[];
    uint32_t smb = smem_u32(sm);

    const int tid = threadIdx.x, lane = tid & 31, warp = tid >> 5;
    const int mtile = blockIdx.x, ntile = blockIdx.y;
    const __half* gA = g_w + (size_t)(mtile * BM) * CC;

    const int wm = warp >> 1, wn = warp & 1;
    const int lr = lane & 15;
    const int lh = (lane >> 4) * 8;
    const uint32_t aoff  = (uint32_t)((wm * 16 + lr) * AST + lh) * 2;
    const uint32_t boff0 = (uint32_t)(A_H + (wn * 48 + lr) * AST + lh) * 2;
    const int g = lane >> 2, cp2 = (lane & 3) * 2;
    const int o0 = mtile * BM + wm * 16;
    const float bv0 = bias[o0 + g], bv1 = bias[o0 + g + 8];

    // A-part unit loader (u in [0,1024)), B-part unit loader (u in [0,1536))
    auto loadA = [&](uint32_t base, int kc, int u) {
        int r = u >> 4, ku = u & 15;
        cp16(base + (uint32_t)(r * AST + ku * 8) * 2,
             gA + (size_t)r * CC + kc + ku * 8);
    };

    #pragma unroll 1
    for (int step = 0; step < NSTEP; step++) {
        const int pin = step & 1;
        const __half* __restrict__ cin  = g_carry[pin];
        __half* __restrict__ cout = g_carry[pin ^ 1];
        const int h = (step < 47) ? (step + 1) : (93 - step);
        const float* __restrict__ src = (step < 47) ? fea : out;
        const __half* gB = cin + (size_t)(ntile * BN) * CC;

        auto loadB = [&](uint32_t base, int kc, int u) {
            int r = u >> 4, ku = u & 15;
            cp16(base + (uint32_t)(A_H + r * AST + ku * 8) * 2,
                 gB + (size_t)r * CC + kc + ku * 8);
        };
        auto load_unit = [&](uint32_t base, int kc, int u) {
            if (u < AUNITS) loadA(base, kc, u);
            else            loadB(base, kc, u - AUNITS);
        };

        // ---- prefetch A of stages 0,1 BEFORE the barrier (W is step-invariant) ----
        #pragma unroll
        for (int i = 0; i < 4; i++) {
            loadA(smb,           0 * BK, tid + i * 256);
            loadA(smb + STG * 2, 1 * BK, tid + i * 256);
        }

        // ---- grid barrier (skip before step 0: initk ordering comes from launch order) ----
        if (step > 0) {
            if (tid == 0) {
                __threadfence();
                atomicAdd(&g_bar, 1u);
                const unsigned target = (unsigned)(NCTA * step);
                unsigned v;
                do {
                    asm volatile("ld.acquire.gpu.u32 %0, [%1];" : "=r"(v) : "l"(&g_bar));
                    if (v < target) __nanosleep(64);
                } while (v < target);
            }
            __syncthreads();
        }

        // ---- B loads for stages 0,1 ----
        #pragma unroll
        for (int i = 0; i < 6; i++) loadB(smb, 0, tid + i * 256);
        cp_commit();                               // G0 = A0 + A1 + B0
        #pragma unroll
        for (int i = 0; i < 6; i++) loadB(smb + STG * 2, BK, tid + i * 256);
        cp_commit();                               // G1 = B1

        float acc[6][4];
        #pragma unroll
        for (int ni = 0; ni < 6; ni++)
            #pragma unroll
            for (int e = 0; e < 4; e++) acc[ni][e] = 0.f;

        int s_cons = 0, s_prod = 2;
        #pragma unroll 1
        for (int it = 0; it < KITER; it++) {
            cp_wait1();
            __syncthreads();
            uint32_t base = smb + (uint32_t)(s_cons * STG) * 2;

            uint32_t a[2][4], b[2][3][4];
            ldsm4(base + aoff, a[0]);
            #pragma unroll
            for (int nb = 0; nb < 3; nb++)
                ldsm4(base + boff0 + (uint32_t)(nb * 16 * AST) * 2, b[0][nb]);

            const int pf = (it + NST - 1 < KITER);
            uint32_t pbase = smb + (uint32_t)(s_prod * STG) * 2;
            const int pkc = (it + NST - 1) * BK;

            #pragma unroll
            for (int kk = 0; kk < BK / 16; kk++) {
                int cur = kk & 1, nxt = cur ^ 1;
                if (kk + 1 < BK / 16) {
                    uint32_t ko = (uint32_t)((kk + 1) * 16) * 2;
                    ldsm4(base + aoff + ko, a[nxt]);
                    #pragma unroll
                    for (int nb = 0; nb < 3; nb++)
                        ldsm4(base + boff0 + (uint32_t)(nb * 16 * AST) * 2 + ko, b[nxt][nb]);
                    // spread next-stage loads: 2 units/thread over 5 k-blocks (2560 total)
                    if (pf && kk < 5) {
                        load_unit(pbase, pkc, kk * 512 + tid);
                        load_unit(pbase, pkc, kk * 512 + 256 + tid);
                    }
                }
                #pragma unroll
                for (int nb = 0; nb < 3; nb++) {
                    mma16816(acc[2 * nb],     a[cur], b[cur][nb][0], b[cur][nb][2]);
                    mma16816(acc[2 * nb + 1], a[cur], b[cur][nb][1], b[cur][nb][3]);
                }
            }
            cp_commit();   // empty group when pf==0 keeps wait counts aligned
            s_cons = (s_cons == NST - 1) ? 0 : s_cons + 1;
            s_prod = (s_prod == NST - 1) ? 0 : s_prod + 1;
        }

        // ---- epilogue: relu+bias+residual, store out, transpose-staged carry write ----
        __syncthreads();   // stage reads done; reuse smem as transpose tile
        #pragma unroll
        for (int ni = 0; ni < 6; ni++)
            #pragma unroll
            for (int e = 0; e < 4; e++) {
                int o_l = wm * 16 + g + (e >> 1) * 8;          // 0..63
                int j_l = wn * 48 + ni * 8 + cp2 + (e & 1);    // 0..95 (== w, since BN==WWD)
                int o = mtile * BM + o_l;
                size_t idx = (size_t)(ntile * CC + o) * HWP + (size_t)h * WWD + j_l;
                float v = acc[ni][e] + ((e >> 1) ? bv1 : bv0);
                v = fmaxf(v, 0.f) + src[idx];
                out[idx] = v;
                sm[j_l * TPAD + o_l] = __float2half(v);
            }
        __syncthreads();
        // coalesced carry writes: 96 rows x 8 segs = 768 16B segments, 3 per thread
        #pragma unroll
        for (int t2 = 0; t2 < 3; t2++) {
            int seg = tid + t2 * 256;
            int j_l = seg >> 3, os = (seg & 7) * 8;
            uint4 val = *reinterpret_cast<const uint4*>(&sm[j_l * TPAD + os]);
            *reinterpret_cast<uint4*>(&cout[(size_t)(ntile * BN + j_l) * CC + mtile * BM + os]) = val;
        }
        __syncthreads();   // carry/transpose reads done before next step's A prefetch
    }
}

// ---------------- prep kernels ----------------
__global__ void wprep(const float* __restrict__ W) {
    int i = blockIdx.x * 256 + threadIdx.x;
    if (i >= CC * CC) return;
    g_w[i] = __float2half(W[(size_t)i * 9 + 4]);   // center tap of KH=9
}

__global__ void initk(const float* __restrict__ fea, float* __restrict__ out) {
    int i = blockIdx.x * 256 + threadIdx.x;
    if (i >= NCOL * CC) return;
    int o = i & (CC - 1), j = i >> 11;
    int n = j / WWD, w = j - n * WWD;
    size_t gidx = (size_t)(n * CC + o) * HWP + w;   // h = 0
    float v = fea[gidx];
    out[gidx] = v;                                   // down[0] = x[0]
    g_carry[0][(size_t)j * CC + o] = __float2half(v);
}

// ---------------- launch ----------------
extern "C" void kernel_launch(void* const* d_in, const int* in_sizes, int n_in,
                              void* d_out, int out_size)
{
    const float* fea = (const float*)d_in[0];
    const float* W   = (const float*)d_in[1];
    const float* b   = (const float*)d_in[2];
    float* out = (float*)d_out;

    cudaFuncSetAttribute(steps_kernel, cudaFuncAttributeMaxDynamicSharedMemorySize, SMEM_BYTES);

    void* bar_addr = nullptr;
    cudaGetSymbolAddress(&bar_addr, g_bar);
    cudaMemsetAsync(bar_addr, 0, sizeof(unsigned));   // reset barrier each launch/replay

    wprep<<<(CC * CC + 255) / 256, 256>>>(W);
    initk<<<(NCOL * CC + 255) / 256, 256>>>(fea, out);

    steps_kernel<<<dim3(32, 4), 256, SMEM_BYTES>>>(b, fea, out);
}